// round 12
// baseline (speedup 1.0000x reference)
#include <cuda_runtime.h>
#include <cuda_bf16.h>
#include <cstdint>
#include <math.h>

#define BB      4
#define LL      1024
#define DIMV    512
#define VOCABN  10000
#define DEPTHN  3
#define DSTATE  16
#define DCONVN  4
#define DINNER  1024
#define DTRANK  32
#define HEADSN  8
#define DH      64
#define CTXN    98
#define NROWS   (BB*LL)          /* 4096 */

typedef unsigned int u32;

// ---------------- scratch (module globals; no cudaMalloc) ----------------
__device__ float g_h[NROWS*DIMV];
__device__ float g_nrm[NROWS*DIMV];
__device__ float g_xz[NROWS*2*DINNER];
__device__ float g_u[NROWS*DINNER];
__device__ float g_xdbl[NROWS*(DTRANK+2*DSTATE)];
__device__ float g_delta[NROWS*DINNER];
__device__ float g_y[NROWS*DINNER];
__device__ float g_q[NROWS*DIMV];
__device__ float g_kv[DEPTHN*BB*CTXN*2*DIMV];   /* per-layer fused K|V */
__device__ float g_probs[BB*HEADSN*LL*CTXN];
__device__ float g_ao[NROWS*DIMV];

__device__ __forceinline__ float siluf(float x) {
    return x / (1.0f + __expf(-x));
}

// =========================================================================
// Tensor-core GEMM (round-5 exact): C[M,N] = A[M,K] @ W[N,K]^T (+bias)(+C)
// bf16 3-term split in-loop, fp32 accumulate. K % 32 == 0.
// =========================================================================
#define BM 128
#define BN 64
#define BKT 32
#define PROW 40   /* bf16 elems per smem row */

__device__ __forceinline__ u32 ld32bf(const __nv_bfloat16* p) {
    return *reinterpret_cast<const u32*>(p);
}

__device__ __forceinline__ void mma16816(float* c, const u32* a, const u32* b) {
    asm volatile(
        "mma.sync.aligned.m16n8k16.row.col.f32.bf16.bf16.f32 "
        "{%0,%1,%2,%3}, {%4,%5,%6,%7}, {%8,%9}, {%0,%1,%2,%3};\n"
        : "+f"(c[0]), "+f"(c[1]), "+f"(c[2]), "+f"(c[3])
        : "r"(a[0]), "r"(a[1]), "r"(a[2]), "r"(a[3]), "r"(b[0]), "r"(b[1]));
}

__device__ __forceinline__ void stage_split(float v, __nv_bfloat16* hp, __nv_bfloat16* lp) {
    __nv_bfloat16 h = __float2bfloat16(v);
    *hp = h;
    *lp = __float2bfloat16(v - __bfloat162float(h));
}

__global__ void __launch_bounds__(256)
hgemm_k(const float* __restrict__ A, int lda,
        const float* __restrict__ W, int ldw,
        const float* __restrict__ bias,
        float* __restrict__ C, int ldc,
        int M, int N, int K, int beta)
{
    __shared__ __nv_bfloat16 Ah[BM*PROW];
    __shared__ __nv_bfloat16 Al[BM*PROW];
    __shared__ __nv_bfloat16 Wh[BN*PROW];
    __shared__ __nv_bfloat16 Wl[BN*PROW];

    int bm = blockIdx.y * BM, bn = blockIdx.x * BN;
    int tid = threadIdx.x;
    int warp = tid >> 5, lane = tid & 31;
    int wm = warp >> 1, wn = warp & 1;        // 4x2 warp grid, warp tile 32x32
    int g = lane >> 2, cq = lane & 3;         // mma fragment coords

    float acc[2][4][4];
#pragma unroll
    for (int mt = 0; mt < 2; mt++)
#pragma unroll
        for (int nt = 0; nt < 4; nt++)
#pragma unroll
            for (int j = 0; j < 4; j++) acc[mt][nt][j] = 0.f;

    for (int k0 = 0; k0 < K; k0 += BKT) {
        // ---- stage A tile: 128 rows x 32 cols ----
#pragma unroll
        for (int it = 0; it < 4; it++) {
            int i = tid + it*256;             // 0..1023
            int r = i >> 3, c4 = (i & 7) << 2;
            int gr = bm + r;
            float4 v = make_float4(0.f,0.f,0.f,0.f);
            if (gr < M) v = *(const float4*)&A[(long)gr*lda + k0 + c4];
            int sb = r*PROW + c4;
            stage_split(v.x, &Ah[sb+0], &Al[sb+0]);
            stage_split(v.y, &Ah[sb+1], &Al[sb+1]);
            stage_split(v.z, &Ah[sb+2], &Al[sb+2]);
            stage_split(v.w, &Ah[sb+3], &Al[sb+3]);
        }
        // ---- stage W tile: 64 rows x 32 cols ----
#pragma unroll
        for (int it = 0; it < 2; it++) {
            int i = tid + it*256;             // 0..511
            int r = i >> 3, c4 = (i & 7) << 2;
            int gn = bn + r;
            float4 v = make_float4(0.f,0.f,0.f,0.f);
            if (gn < N) v = *(const float4*)&W[(long)gn*ldw + k0 + c4];
            int sb = r*PROW + c4;
            stage_split(v.x, &Wh[sb+0], &Wl[sb+0]);
            stage_split(v.y, &Wh[sb+1], &Wl[sb+1]);
            stage_split(v.z, &Wh[sb+2], &Wl[sb+2]);
            stage_split(v.w, &Wh[sb+3], &Wl[sb+3]);
        }
        __syncthreads();

#pragma unroll
        for (int ks = 0; ks < 2; ks++) {
            u32 ah[2][4], al[2][4], bh[4][2], bl[4][2];
#pragma unroll
            for (int mt = 0; mt < 2; mt++) {
                int base = (wm*32 + mt*16 + g)*PROW + ks*16 + 2*cq;
                ah[mt][0] = ld32bf(&Ah[base]);
                ah[mt][1] = ld32bf(&Ah[base + 8*PROW]);
                ah[mt][2] = ld32bf(&Ah[base + 8]);
                ah[mt][3] = ld32bf(&Ah[base + 8*PROW + 8]);
                al[mt][0] = ld32bf(&Al[base]);
                al[mt][1] = ld32bf(&Al[base + 8*PROW]);
                al[mt][2] = ld32bf(&Al[base + 8]);
                al[mt][3] = ld32bf(&Al[base + 8*PROW + 8]);
            }
#pragma unroll
            for (int nt = 0; nt < 4; nt++) {
                int base = (wn*32 + nt*8 + g)*PROW + ks*16 + 2*cq;
                bh[nt][0] = ld32bf(&Wh[base]);
                bh[nt][1] = ld32bf(&Wh[base + 8]);
                bl[nt][0] = ld32bf(&Wl[base]);
                bl[nt][1] = ld32bf(&Wl[base + 8]);
            }
#pragma unroll
            for (int mt = 0; mt < 2; mt++)
#pragma unroll
                for (int nt = 0; nt < 4; nt++) {
                    mma16816(acc[mt][nt], ah[mt], bh[nt]);   // hi*hi
                    mma16816(acc[mt][nt], al[mt], bh[nt]);   // lo*hi
                    mma16816(acc[mt][nt], ah[mt], bl[nt]);   // hi*lo
                }
        }
        __syncthreads();
    }

    // ---- epilogue ----
#pragma unroll
    for (int mt = 0; mt < 2; mt++) {
        int r0 = bm + wm*32 + mt*16 + g;
#pragma unroll
        for (int nt = 0; nt < 4; nt++) {
            int n0 = bn + wn*32 + nt*8 + 2*cq;
            float b0v = 0.f, b1v = 0.f;
            if (bias) {
                if (n0   < N) b0v = bias[n0];
                if (n0+1 < N) b1v = bias[n0+1];
            }
#pragma unroll
            for (int half = 0; half < 2; half++) {
                int r = r0 + half*8;
                if (r >= M) continue;
                float* p = &C[(long)r*ldc + n0];
                if (n0 < N) {
                    float o = acc[mt][nt][half*2+0] + b0v;
                    if (beta) o += p[0];
                    p[0] = o;
                }
                if (n0+1 < N) {
                    float o = acc[mt][nt][half*2+1] + b1v;
                    if (beta) o += p[1];
                    p[1] = o;
                }
            }
        }
    }
}

// ---------------- layernorm: one block (256 thr) per row of 512 ----------
__global__ void __launch_bounds__(256)
layernorm_k(const float* __restrict__ x, const float* __restrict__ g,
            const float* __restrict__ bta, float* __restrict__ outp)
{
    int row = blockIdx.x;
    const float* xr = x + (long)row*DIMV;
    int tid = threadIdx.x;
    float v0 = xr[tid], v1 = xr[tid+256];

    __shared__ float red[8];
    float s = v0 + v1;
#pragma unroll
    for (int o = 16; o; o >>= 1) s += __shfl_xor_sync(0xffffffffu, s, o);
    if ((tid & 31) == 0) red[tid >> 5] = s;
    __syncthreads();
    if (tid < 8) {
        s = red[tid];
#pragma unroll
        for (int o = 4; o; o >>= 1) s += __shfl_xor_sync(0xffu, s, o);
        if (tid == 0) red[0] = s;
    }
    __syncthreads();
    float mu = red[0] * (1.0f/DIMV);
    float d0 = v0 - mu, d1 = v1 - mu;

    __shared__ float red2[8];
    float qv = d0*d0 + d1*d1;
#pragma unroll
    for (int o = 16; o; o >>= 1) qv += __shfl_xor_sync(0xffffffffu, qv, o);
    if ((tid & 31) == 0) red2[tid >> 5] = qv;
    __syncthreads();
    if (tid < 8) {
        qv = red2[tid];
#pragma unroll
        for (int o = 4; o; o >>= 1) qv += __shfl_xor_sync(0xffu, qv, o);
        if (tid == 0) red2[0] = qv;
    }
    __syncthreads();
    float rstd = rsqrtf(red2[0] * (1.0f/DIMV) + 1e-5f);
    outp[(long)row*DIMV + tid]       = d0*rstd*g[tid]     + bta[tid];
    outp[(long)row*DIMV + tid + 256] = d1*rstd*g[tid+256] + bta[tid+256];
}

// ---------------- embedding ----------------
__global__ void embed_k(const int* __restrict__ x, const float* __restrict__ tok,
                        const float* __restrict__ pos)
{
    int idx = blockIdx.x*blockDim.x + threadIdx.x;
    if (idx >= NROWS*DIMV) return;
    int d = idx & (DIMV-1);
    int row = idx >> 9;
    int l = row & (LL-1);
    int t = x[row];
    g_h[idx] = tok[(long)t*DIMV + d] + pos[(long)l*DIMV + d];
}

// ---------------- causal depthwise conv + silu ----------------
__global__ void conv_silu_k(const float* __restrict__ w, const float* __restrict__ cb)
{
    int idx = blockIdx.x*blockDim.x + threadIdx.x;
    if (idx >= NROWS*DINNER) return;
    int d = idx & (DINNER-1);
    int row = idx >> 10;
    int l = row & (LL-1);
    int b = row >> 10;
    float acc = cb[d];
#pragma unroll
    for (int j = 0; j < DCONVN; j++) {
        int ll = l - (DCONVN-1) + j;
        if (ll >= 0)
            acc += w[d*DCONVN + j] * g_xz[((long)(b*LL + ll))*(2*DINNER) + d];
    }
    g_u[idx] = siluf(acc);
}

// ---------------- softplus on delta ----------------
__global__ void softplus_k()
{
    int idx = blockIdx.x*blockDim.x + threadIdx.x;
    if (idx >= NROWS*DINNER) return;
    float x = g_delta[idx];
    g_delta[idx] = (x > 20.f) ? x : log1pf(expf(x));
}

// ---------------- selective scan: 16 states -> 16 lanes ----------------
__global__ void __launch_bounds__(256)
scan_k(const float* __restrict__ A_log, const float* __restrict__ D_skip)
{
    int b = blockIdx.y;
    int dbase = blockIdx.x * 16;
    int tid = threadIdx.x;
    int w = tid >> 5, lane = tid & 31;
    int d = dbase + (w << 1) + (lane >> 4);
    int s = lane & 15;

    float a  = -__expf(A_log[d*DSTATE + s]);
    float Dv = D_skip[d];
    float h  = 0.f;

    const float* dl = g_delta + (long)b*LL*DINNER + d;
    const float* uu = g_u     + (long)b*LL*DINNER + d;
    const float* bc = g_xdbl  + (long)b*LL*(DTRANK+2*DSTATE);
    float*       yo = g_y     + (long)b*LL*DINNER + d;

#pragma unroll 4
    for (int t = 0; t < LL; t++) {
        float dt = dl[(long)t*DINNER];
        float ut = uu[(long)t*DINNER];
        float Bt = bc[t*64 + DTRANK + s];
        float Ct = bc[t*64 + DTRANK + DSTATE + s];
        h = __expf(dt*a)*h + (dt*ut)*Bt;
        float p = h*Ct;
        p += __shfl_xor_sync(0xffffffffu, p, 8);
        p += __shfl_xor_sync(0xffffffffu, p, 4);
        p += __shfl_xor_sync(0xffffffffu, p, 2);
        p += __shfl_xor_sync(0xffffffffu, p, 1);
        if (s == 0) yo[(long)t*DINNER] = p + ut*Dv;
    }
}

// ---------------- gate: y *= silu(z) ----------------
__global__ void gate_k()
{
    int idx = blockIdx.x*blockDim.x + threadIdx.x;
    if (idx >= NROWS*DINNER) return;
    int d = idx & (DINNER-1);
    int row = idx >> 10;
    float z = g_xz[(long)row*(2*DINNER) + DINNER + d];
    g_y[idx] *= siluf(z);
}

// ---------------- attention scores: grid (B*H, L/128), 128 thr ----------
__global__ void __launch_bounds__(128)
attn_scores_k(const float* __restrict__ kvp)
{
    __shared__ float ks[CTXN*DH];
    int bh = blockIdx.x;
    int b = bh >> 3, hh = bh & 7;
    for (int i = threadIdx.x; i < CTXN*DH; i += 128)
        ks[i] = kvp[((long)(b*CTXN + (i >> 6)))*(2*DIMV) + hh*DH + (i & 63)];
    __syncthreads();

    int l = blockIdx.y*128 + threadIdx.x;
    float qr[DH];
    const float* qp = g_q + ((long)(b*LL + l))*DIMV + hh*DH;
#pragma unroll
    for (int j = 0; j < DH; j++) qr[j] = qp[j];

    float* sp = g_probs + ((long)(bh*LL + l))*CTXN;
    for (int ss = 0; ss < CTXN; ss++) {
        float acc = 0.f;
#pragma unroll
        for (int j = 0; j < DH; j++) acc += qr[j]*ks[ss*DH + j];
        sp[ss] = acc * 0.125f;   // 1/sqrt(64)
    }
}

// ---------------- softmax over S=98: one warp per row ----------------
__global__ void __launch_bounds__(256)
softmax_k()
{
    int row = blockIdx.x*8 + (threadIdx.x >> 5);
    int lane = threadIdx.x & 31;
    float* p = g_probs + (long)row*CTXN;
    float v0 = p[lane];
    float v1 = p[lane+32];
    float v2 = p[lane+64];
    float v3 = (lane+96 < CTXN) ? p[lane+96] : -1e30f;
    float m = fmaxf(fmaxf(v0,v1), fmaxf(v2,v3));
#pragma unroll
    for (int o = 16; o; o >>= 1) m = fmaxf(m, __shfl_xor_sync(0xffffffffu, m, o));
    v0 = __expf(v0 - m); v1 = __expf(v1 - m); v2 = __expf(v2 - m);
    v3 = (lane+96 < CTXN) ? __expf(v3 - m) : 0.f;
    float s = v0+v1+v2+v3;
#pragma unroll
    for (int o = 16; o; o >>= 1) s += __shfl_xor_sync(0xffffffffu, s, o);
    float inv = 1.f/s;
    p[lane] = v0*inv; p[lane+32] = v1*inv; p[lane+64] = v2*inv;
    if (lane+96 < CTXN) p[lane+96] = v3*inv;
}

// ---------------- attn head-mean -> d_out region ----------------
__global__ void attn_mean_k(float* __restrict__ outp)
{
    int idx = blockIdx.x*blockDim.x + threadIdx.x;
    if (idx >= BB*LL*CTXN) return;
    int s = idx % CTXN;
    int bl = idx / CTXN;
    int l = bl & (LL-1);
    int b = bl >> 10;
    float acc = 0.f;
#pragma unroll
    for (int hh = 0; hh < HEADSN; hh++)
        acc += g_probs[((long)((b*HEADSN + hh)*LL + l))*CTXN + s];
    outp[idx] = acc * (1.0f/HEADSN);
}

// ---------------- attn @ V: grid (B*H, L/128), 128 thr ----------------
__global__ void __launch_bounds__(128)
attn_av_k(const float* __restrict__ kvp)
{
    __shared__ float vs[CTXN*DH];
    int bh = blockIdx.x;
    int b = bh >> 3, hh = bh & 7;
    for (int i = threadIdx.x; i < CTXN*DH; i += 128)
        vs[i] = kvp[((long)(b*CTXN + (i >> 6)))*(2*DIMV) + DIMV + hh*DH + (i & 63)];
    __syncthreads();

    int l = blockIdx.y*128 + threadIdx.x;
    const float* pp = g_probs + ((long)(bh*LL + l))*CTXN;
    float acc[DH];
#pragma unroll
    for (int j = 0; j < DH; j++) acc[j] = 0.f;
    for (int ss = 0; ss < CTXN; ss++) {
        float pv = pp[ss];
#pragma unroll
        for (int j = 0; j < DH; j++) acc[j] += pv*vs[ss*DH + j];
    }
    float* op = g_ao + ((long)(b*LL + l))*DIMV + hh*DH;
#pragma unroll
    for (int j = 0; j < DH; j++) op[j] = acc[j];
}

// =======================================================================
extern "C" void kernel_launch(void* const* d_in, const int* in_sizes, int n_in,
                              void* d_out, int out_size)
{
    (void)in_sizes; (void)n_in; (void)out_size;
    const int*   x          = (const int*)  d_in[0];
    const float* context    = (const float*)d_in[1];
    const float* tok_emb    = (const float*)d_in[2];
    const float* pos_emb    = (const float*)d_in[3];
    const float* ln1_g      = (const float*)d_in[4];
    const float* ln1_b      = (const float*)d_in[5];
    const float* in_w       = (const float*)d_in[6];
    const float* conv_w     = (const float*)d_in[7];
    const float* conv_b     = (const float*)d_in[8];
    const float* xproj_w    = (const float*)d_in[9];
    const float* dt_w       = (const float*)d_in[10];
    const float* dt_b       = (const float*)d_in[11];
    const float* A_log      = (const float*)d_in[12];
    const float* D_skip     = (const float*)d_in[13];
    const float* mamba_out_w= (const float*)d_in[14];
    const float* ln2_g      = (const float*)d_in[15];
    const float* ln2_b      = (const float*)d_in[16];
    const float* attn_in_w  = (const float*)d_in[17];
    const float* attn_in_b  = (const float*)d_in[18];
    const float* attn_out_w = (const float*)d_in[19];
    const float* attn_out_b = (const float*)d_in[20];
    const float* lnf_g      = (const float*)d_in[21];
    const float* lnf_b      = (const float*)d_in[22];
    const float* logit_w    = (const float*)d_in[23];
    const float* logit_b    = (const float*)d_in[24];
    float* outp = (float*)d_out;

    float *h, *nrm, *xz, *u, *xdbl, *delta, *y, *q, *kv, *ao;
    cudaGetSymbolAddress((void**)&h,    g_h);
    cudaGetSymbolAddress((void**)&nrm,  g_nrm);
    cudaGetSymbolAddress((void**)&xz,   g_xz);
    cudaGetSymbolAddress((void**)&u,    g_u);
    cudaGetSymbolAddress((void**)&xdbl, g_xdbl);
    cudaGetSymbolAddress((void**)&delta,g_delta);
    cudaGetSymbolAddress((void**)&y,    g_y);
    cudaGetSymbolAddress((void**)&q,    g_q);
    cudaGetSymbolAddress((void**)&kv,   g_kv);
    cudaGetSymbolAddress((void**)&ao,   g_ao);

    auto gemm = [](const float* A, int lda, const float* W, int ldw,
                   const float* bias, float* C, int ldc,
                   int M, int N, int K, int beta) {
        dim3 grid((N + BN - 1)/BN, (M + BM - 1)/BM);
        hgemm_k<<<grid, 256>>>(A, lda, W, ldw, bias, C, ldc, M, N, K, beta);
    };

    const int NTH = 256;
    const long KVSZ = (long)BB*CTXN*2*DIMV;

    // Launch order: embed(1), kv0(2), kv1(3), kv2(4), LN1(5), in_proj(6) <- ncu -s5 -c1
    embed_k<<<(NROWS*DIMV + NTH-1)/NTH, NTH>>>(x, tok_emb, pos_emb);

    // K/V depend only on context — hoist all layers, fused K|V (N=1024)
    for (int i = 0; i < DEPTHN; i++) {
        const float* aw = attn_in_w + (long)i*3*DIMV*DIMV;
        const float* ab = attn_in_b + (long)i*3*DIMV;
        gemm(context, DIMV, aw + (long)DIMV*DIMV, DIMV, ab + DIMV,
             kv + (long)i*KVSZ, 2*DIMV, BB*CTXN, 2*DIMV, DIMV, 0);
    }

    for (int i = 0; i < DEPTHN; i++) {
        // ---- mamba block ----
        layernorm_k<<<NROWS, 256>>>(h, ln1_g + i*DIMV, ln1_b + i*DIMV, nrm);
        gemm(nrm, DIMV, in_w + (long)i*2*DINNER*DIMV, DIMV, nullptr,
             xz, 2*DINNER, NROWS, 2*DINNER, DIMV, 0);
        conv_silu_k<<<(NROWS*DINNER + NTH-1)/NTH, NTH>>>(
            conv_w + (long)i*DINNER*DCONVN, conv_b + (long)i*DINNER);
        gemm(u, DINNER, xproj_w + (long)i*(DTRANK+2*DSTATE)*DINNER, DINNER, nullptr,
             xdbl, DTRANK+2*DSTATE, NROWS, DTRANK+2*DSTATE, DINNER, 0);
        gemm(xdbl, DTRANK+2*DSTATE, dt_w + (long)i*DINNER*DTRANK, DTRANK,
             dt_b + (long)i*DINNER, delta, DINNER, NROWS, DINNER, DTRANK, 0);
        softplus_k<<<(NROWS*DINNER + NTH-1)/NTH, NTH>>>();
        scan_k<<<dim3(DINNER/16, BB), 256>>>(
            A_log + (long)i*DINNER*DSTATE, D_skip + (long)i*DINNER);
        gate_k<<<(NROWS*DINNER + NTH-1)/NTH, NTH>>>();
        gemm(y, DINNER, mamba_out_w + (long)i*DIMV*DINNER, DINNER, nullptr,
             h, DIMV, NROWS, DIMV, DINNER, 1);          // fused residual add

        // ---- cross attention ----
        layernorm_k<<<NROWS, 256>>>(h, ln2_g + i*DIMV, ln2_b + i*DIMV, nrm);
        const float* aw = attn_in_w + (long)i*3*DIMV*DIMV;
        const float* ab = attn_in_b + (long)i*3*DIMV;
        gemm(nrm, DIMV, aw, DIMV, ab, q, DIMV, NROWS, DIMV, DIMV, 0);
        const float* kvi = kv + (long)i*KVSZ;
        attn_scores_k<<<dim3(BB*HEADSN, LL/128), 128>>>(kvi);
        softmax_k<<<(BB*HEADSN*LL)/8, 256>>>();
        attn_mean_k<<<(BB*LL*CTXN + NTH-1)/NTH, NTH>>>(
            outp + (long)BB*LL*VOCABN + (long)i*BB*LL*CTXN);
        attn_av_k<<<dim3(BB*HEADSN, LL/128), 128>>>(kvi);
        gemm(ao, DIMV, attn_out_w + (long)i*DIMV*DIMV, DIMV,
             attn_out_b + (long)i*DIMV, h, DIMV, NROWS, DIMV, DIMV, 1);  // fused add
    }

    // ---- final LN + logits ----
    layernorm_k<<<NROWS, 256>>>(h, lnf_g, lnf_b, nrm);
    gemm(nrm, DIMV, logit_w, DIMV, logit_b, outp, VOCABN, NROWS, VOCABN, DIMV, 0);
}

// round 13
// speedup vs baseline: 1.0025x; 1.0025x over previous
#include <cuda_runtime.h>
#include <cuda_bf16.h>
#include <cstdint>
#include <math.h>

#define BB      4
#define LL      1024
#define DIMV    512
#define VOCABN  10000
#define DEPTHN  3
#define DSTATE  16
#define DCONVN  4
#define DINNER  1024
#define DTRANK  32
#define HEADSN  8
#define DH      64
#define CTXN    98
#define NROWS   (BB*LL)          /* 4096 */

typedef unsigned int u32;

// ---------------- scratch (module globals; no cudaMalloc) ----------------
__device__ float g_h[NROWS*DIMV];
__device__ float g_nrm[NROWS*DIMV];
__device__ float g_xz[NROWS*2*DINNER];
__device__ float g_u[NROWS*DINNER];
__device__ float g_xdbl[NROWS*(DTRANK+2*DSTATE)];
__device__ float g_delta[NROWS*DINNER];
__device__ float g_y[NROWS*DINNER];
__device__ float g_q[NROWS*DIMV];
__device__ float g_kv[DEPTHN*BB*CTXN*2*DIMV];   /* per-layer fused K|V */
__device__ float g_probs[BB*HEADSN*LL*CTXN];
__device__ float g_ao[NROWS*DIMV];

__device__ __forceinline__ float siluf(float x) {
    return x / (1.0f + __expf(-x));
}

// =========================================================================
// Tensor-core GEMM (round-5 exact): C[M,N] = A[M,K] @ W[N,K]^T (+bias)(+C)
// bf16 3-term split in-loop, fp32 accumulate. K % 32 == 0.
// =========================================================================
#define BM 128
#define BN 64
#define BKT 32
#define PROW 40   /* bf16 elems per smem row */

__device__ __forceinline__ u32 ld32bf(const __nv_bfloat16* p) {
    return *reinterpret_cast<const u32*>(p);
}

__device__ __forceinline__ void mma16816(float* c, const u32* a, const u32* b) {
    asm volatile(
        "mma.sync.aligned.m16n8k16.row.col.f32.bf16.bf16.f32 "
        "{%0,%1,%2,%3}, {%4,%5,%6,%7}, {%8,%9}, {%0,%1,%2,%3};\n"
        : "+f"(c[0]), "+f"(c[1]), "+f"(c[2]), "+f"(c[3])
        : "r"(a[0]), "r"(a[1]), "r"(a[2]), "r"(a[3]), "r"(b[0]), "r"(b[1]));
}

__device__ __forceinline__ void stage_split(float v, __nv_bfloat16* hp, __nv_bfloat16* lp) {
    __nv_bfloat16 h = __float2bfloat16(v);
    *hp = h;
    *lp = __float2bfloat16(v - __bfloat162float(h));
}

__global__ void __launch_bounds__(256)
hgemm_k(const float* __restrict__ A, int lda,
        const float* __restrict__ W, int ldw,
        const float* __restrict__ bias,
        float* __restrict__ C, int ldc,
        int M, int N, int K, int beta)
{
    __shared__ __nv_bfloat16 Ah[BM*PROW];
    __shared__ __nv_bfloat16 Al[BM*PROW];
    __shared__ __nv_bfloat16 Wh[BN*PROW];
    __shared__ __nv_bfloat16 Wl[BN*PROW];

    int bm = blockIdx.y * BM, bn = blockIdx.x * BN;
    int tid = threadIdx.x;
    int warp = tid >> 5, lane = tid & 31;
    int wm = warp >> 1, wn = warp & 1;        // 4x2 warp grid, warp tile 32x32
    int g = lane >> 2, cq = lane & 3;         // mma fragment coords

    float acc[2][4][4];
#pragma unroll
    for (int mt = 0; mt < 2; mt++)
#pragma unroll
        for (int nt = 0; nt < 4; nt++)
#pragma unroll
            for (int j = 0; j < 4; j++) acc[mt][nt][j] = 0.f;

    for (int k0 = 0; k0 < K; k0 += BKT) {
        // ---- stage A tile: 128 rows x 32 cols ----
#pragma unroll
        for (int it = 0; it < 4; it++) {
            int i = tid + it*256;             // 0..1023
            int r = i >> 3, c4 = (i & 7) << 2;
            int gr = bm + r;
            float4 v = make_float4(0.f,0.f,0.f,0.f);
            if (gr < M) v = *(const float4*)&A[(long)gr*lda + k0 + c4];
            int sb = r*PROW + c4;
            stage_split(v.x, &Ah[sb+0], &Al[sb+0]);
            stage_split(v.y, &Ah[sb+1], &Al[sb+1]);
            stage_split(v.z, &Ah[sb+2], &Al[sb+2]);
            stage_split(v.w, &Ah[sb+3], &Al[sb+3]);
        }
        // ---- stage W tile: 64 rows x 32 cols ----
#pragma unroll
        for (int it = 0; it < 2; it++) {
            int i = tid + it*256;             // 0..511
            int r = i >> 3, c4 = (i & 7) << 2;
            int gn = bn + r;
            float4 v = make_float4(0.f,0.f,0.f,0.f);
            if (gn < N) v = *(const float4*)&W[(long)gn*ldw + k0 + c4];
            int sb = r*PROW + c4;
            stage_split(v.x, &Wh[sb+0], &Wl[sb+0]);
            stage_split(v.y, &Wh[sb+1], &Wl[sb+1]);
            stage_split(v.z, &Wh[sb+2], &Wl[sb+2]);
            stage_split(v.w, &Wh[sb+3], &Wl[sb+3]);
        }
        __syncthreads();

#pragma unroll
        for (int ks = 0; ks < 2; ks++) {
            u32 ah[2][4], al[2][4], bh[4][2], bl[4][2];
#pragma unroll
            for (int mt = 0; mt < 2; mt++) {
                int base = (wm*32 + mt*16 + g)*PROW + ks*16 + 2*cq;
                ah[mt][0] = ld32bf(&Ah[base]);
                ah[mt][1] = ld32bf(&Ah[base + 8*PROW]);
                ah[mt][2] = ld32bf(&Ah[base + 8]);
                ah[mt][3] = ld32bf(&Ah[base + 8*PROW + 8]);
                al[mt][0] = ld32bf(&Al[base]);
                al[mt][1] = ld32bf(&Al[base + 8*PROW]);
                al[mt][2] = ld32bf(&Al[base + 8]);
                al[mt][3] = ld32bf(&Al[base + 8*PROW + 8]);
            }
#pragma unroll
            for (int nt = 0; nt < 4; nt++) {
                int base = (wn*32 + nt*8 + g)*PROW + ks*16 + 2*cq;
                bh[nt][0] = ld32bf(&Wh[base]);
                bh[nt][1] = ld32bf(&Wh[base + 8]);
                bl[nt][0] = ld32bf(&Wl[base]);
                bl[nt][1] = ld32bf(&Wl[base + 8]);
            }
#pragma unroll
            for (int mt = 0; mt < 2; mt++)
#pragma unroll
                for (int nt = 0; nt < 4; nt++) {
                    mma16816(acc[mt][nt], ah[mt], bh[nt]);   // hi*hi
                    mma16816(acc[mt][nt], al[mt], bh[nt]);   // lo*hi
                    mma16816(acc[mt][nt], ah[mt], bl[nt]);   // hi*lo
                }
        }
        __syncthreads();
    }

    // ---- epilogue ----
#pragma unroll
    for (int mt = 0; mt < 2; mt++) {
        int r0 = bm + wm*32 + mt*16 + g;
#pragma unroll
        for (int nt = 0; nt < 4; nt++) {
            int n0 = bn + wn*32 + nt*8 + 2*cq;
            float b0v = 0.f, b1v = 0.f;
            if (bias) {
                if (n0   < N) b0v = bias[n0];
                if (n0+1 < N) b1v = bias[n0+1];
            }
#pragma unroll
            for (int half = 0; half < 2; half++) {
                int r = r0 + half*8;
                if (r >= M) continue;
                float* p = &C[(long)r*ldc + n0];
                if (n0 < N) {
                    float o = acc[mt][nt][half*2+0] + b0v;
                    if (beta) o += p[0];
                    p[0] = o;
                }
                if (n0+1 < N) {
                    float o = acc[mt][nt][half*2+1] + b1v;
                    if (beta) o += p[1];
                    p[1] = o;
                }
            }
        }
    }
}

// ---------------- layernorm: one block (256 thr) per row of 512 ----------
__global__ void __launch_bounds__(256)
layernorm_k(const float* __restrict__ x, const float* __restrict__ g,
            const float* __restrict__ bta, float* __restrict__ outp)
{
    int row = blockIdx.x;
    const float* xr = x + (long)row*DIMV;
    int tid = threadIdx.x;
    float v0 = xr[tid], v1 = xr[tid+256];

    __shared__ float red[8];
    float s = v0 + v1;
#pragma unroll
    for (int o = 16; o; o >>= 1) s += __shfl_xor_sync(0xffffffffu, s, o);
    if ((tid & 31) == 0) red[tid >> 5] = s;
    __syncthreads();
    if (tid < 8) {
        s = red[tid];
#pragma unroll
        for (int o = 4; o; o >>= 1) s += __shfl_xor_sync(0xffu, s, o);
        if (tid == 0) red[0] = s;
    }
    __syncthreads();
    float mu = red[0] * (1.0f/DIMV);
    float d0 = v0 - mu, d1 = v1 - mu;

    __shared__ float red2[8];
    float qv = d0*d0 + d1*d1;
#pragma unroll
    for (int o = 16; o; o >>= 1) qv += __shfl_xor_sync(0xffffffffu, qv, o);
    if ((tid & 31) == 0) red2[tid >> 5] = qv;
    __syncthreads();
    if (tid < 8) {
        qv = red2[tid];
#pragma unroll
        for (int o = 4; o; o >>= 1) qv += __shfl_xor_sync(0xffu, qv, o);
        if (tid == 0) red2[0] = qv;
    }
    __syncthreads();
    float rstd = rsqrtf(red2[0] * (1.0f/DIMV) + 1e-5f);
    outp[(long)row*DIMV + tid]       = d0*rstd*g[tid]     + bta[tid];
    outp[(long)row*DIMV + tid + 256] = d1*rstd*g[tid+256] + bta[tid+256];
}

// ---------------- embedding ----------------
__global__ void embed_k(const int* __restrict__ x, const float* __restrict__ tok,
                        const float* __restrict__ pos)
{
    int idx = blockIdx.x*blockDim.x + threadIdx.x;
    if (idx >= NROWS*DIMV) return;
    int d = idx & (DIMV-1);
    int row = idx >> 9;
    int l = row & (LL-1);
    int t = x[row];
    g_h[idx] = tok[(long)t*DIMV + d] + pos[(long)l*DIMV + d];
}

// ---------------- causal depthwise conv + silu ----------------
__global__ void conv_silu_k(const float* __restrict__ w, const float* __restrict__ cb)
{
    int idx = blockIdx.x*blockDim.x + threadIdx.x;
    if (idx >= NROWS*DINNER) return;
    int d = idx & (DINNER-1);
    int row = idx >> 10;
    int l = row & (LL-1);
    int b = row >> 10;
    float acc = cb[d];
#pragma unroll
    for (int j = 0; j < DCONVN; j++) {
        int ll = l - (DCONVN-1) + j;
        if (ll >= 0)
            acc += w[d*DCONVN + j] * g_xz[((long)(b*LL + ll))*(2*DINNER) + d];
    }
    g_u[idx] = siluf(acc);
}

// ---------------- softplus on delta ----------------
__global__ void softplus_k()
{
    int idx = blockIdx.x*blockDim.x + threadIdx.x;
    if (idx >= NROWS*DINNER) return;
    float x = g_delta[idx];
    g_delta[idx] = (x > 20.f) ? x : log1pf(expf(x));
}

// ---------------- selective scan: 16 states -> 16 lanes ----------------
__global__ void __launch_bounds__(256)
scan_k(const float* __restrict__ A_log, const float* __restrict__ D_skip)
{
    int b = blockIdx.y;
    int dbase = blockIdx.x * 16;
    int tid = threadIdx.x;
    int w = tid >> 5, lane = tid & 31;
    int d = dbase + (w << 1) + (lane >> 4);
    int s = lane & 15;

    float a  = -__expf(A_log[d*DSTATE + s]);
    float Dv = D_skip[d];
    float h  = 0.f;

    const float* dl = g_delta + (long)b*LL*DINNER + d;
    const float* uu = g_u     + (long)b*LL*DINNER + d;
    const float* bc = g_xdbl  + (long)b*LL*(DTRANK+2*DSTATE);
    float*       yo = g_y     + (long)b*LL*DINNER + d;

#pragma unroll 4
    for (int t = 0; t < LL; t++) {
        float dt = dl[(long)t*DINNER];
        float ut = uu[(long)t*DINNER];
        float Bt = bc[t*64 + DTRANK + s];
        float Ct = bc[t*64 + DTRANK + DSTATE + s];
        h = __expf(dt*a)*h + (dt*ut)*Bt;
        float p = h*Ct;
        p += __shfl_xor_sync(0xffffffffu, p, 8);
        p += __shfl_xor_sync(0xffffffffu, p, 4);
        p += __shfl_xor_sync(0xffffffffu, p, 2);
        p += __shfl_xor_sync(0xffffffffu, p, 1);
        if (s == 0) yo[(long)t*DINNER] = p + ut*Dv;
    }
}

// ---------------- gate: y *= silu(z) ----------------
__global__ void gate_k()
{
    int idx = blockIdx.x*blockDim.x + threadIdx.x;
    if (idx >= NROWS*DINNER) return;
    int d = idx & (DINNER-1);
    int row = idx >> 10;
    float z = g_xz[(long)row*(2*DINNER) + DINNER + d];
    g_y[idx] *= siluf(z);
}

// ---------------- attention scores: grid (B*H, L/128), 128 thr ----------
__global__ void __launch_bounds__(128)
attn_scores_k(const float* __restrict__ kvp)
{
    __shared__ float ks[CTXN*DH];
    int bh = blockIdx.x;
    int b = bh >> 3, hh = bh & 7;
    for (int i = threadIdx.x; i < CTXN*DH; i += 128)
        ks[i] = kvp[((long)(b*CTXN + (i >> 6)))*(2*DIMV) + hh*DH + (i & 63)];
    __syncthreads();

    int l = blockIdx.y*128 + threadIdx.x;
    float qr[DH];
    const float* qp = g_q + ((long)(b*LL + l))*DIMV + hh*DH;
#pragma unroll
    for (int j = 0; j < DH; j++) qr[j] = qp[j];

    float* sp = g_probs + ((long)(bh*LL + l))*CTXN;
    for (int ss = 0; ss < CTXN; ss++) {
        float acc = 0.f;
#pragma unroll
        for (int j = 0; j < DH; j++) acc += qr[j]*ks[ss*DH + j];
        sp[ss] = acc * 0.125f;   // 1/sqrt(64)
    }
}

// ---------------- softmax over S=98: one warp per row ----------------
__global__ void __launch_bounds__(256)
softmax_k()
{
    int row = blockIdx.x*8 + (threadIdx.x >> 5);
    int lane = threadIdx.x & 31;
    float* p = g_probs + (long)row*CTXN;
    float v0 = p[lane];
    float v1 = p[lane+32];
    float v2 = p[lane+64];
    float v3 = (lane+96 < CTXN) ? p[lane+96] : -1e30f;
    float m = fmaxf(fmaxf(v0,v1), fmaxf(v2,v3));
#pragma unroll
    for (int o = 16; o; o >>= 1) m = fmaxf(m, __shfl_xor_sync(0xffffffffu, m, o));
    v0 = __expf(v0 - m); v1 = __expf(v1 - m); v2 = __expf(v2 - m);
    v3 = (lane+96 < CTXN) ? __expf(v3 - m) : 0.f;
    float s = v0+v1+v2+v3;
#pragma unroll
    for (int o = 16; o; o >>= 1) s += __shfl_xor_sync(0xffffffffu, s, o);
    float inv = 1.f/s;
    p[lane] = v0*inv; p[lane+32] = v1*inv; p[lane+64] = v2*inv;
    if (lane+96 < CTXN) p[lane+96] = v3*inv;
}

// ---------------- attn head-mean -> d_out region ----------------
__global__ void attn_mean_k(float* __restrict__ outp)
{
    int idx = blockIdx.x*blockDim.x + threadIdx.x;
    if (idx >= BB*LL*CTXN) return;
    int s = idx % CTXN;
    int bl = idx / CTXN;
    int l = bl & (LL-1);
    int b = bl >> 10;
    float acc = 0.f;
#pragma unroll
    for (int hh = 0; hh < HEADSN; hh++)
        acc += g_probs[((long)((b*HEADSN + hh)*LL + l))*CTXN + s];
    outp[idx] = acc * (1.0f/HEADSN);
}

// ---------------- attn @ V: grid (B*H, L/128), 128 thr ----------------
__global__ void __launch_bounds__(128)
attn_av_k(const float* __restrict__ kvp)
{
    __shared__ float vs[CTXN*DH];
    int bh = blockIdx.x;
    int b = bh >> 3, hh = bh & 7;
    for (int i = threadIdx.x; i < CTXN*DH; i += 128)
        vs[i] = kvp[((long)(b*CTXN + (i >> 6)))*(2*DIMV) + DIMV + hh*DH + (i & 63)];
    __syncthreads();

    int l = blockIdx.y*128 + threadIdx.x;
    const float* pp = g_probs + ((long)(bh*LL + l))*CTXN;
    float acc[DH];
#pragma unroll
    for (int j = 0; j < DH; j++) acc[j] = 0.f;
    for (int ss = 0; ss < CTXN; ss++) {
        float pv = pp[ss];
#pragma unroll
        for (int j = 0; j < DH; j++) acc[j] += pv*vs[ss*DH + j];
    }
    float* op = g_ao + ((long)(b*LL + l))*DIMV + hh*DH;
#pragma unroll
    for (int j = 0; j < DH; j++) op[j] = acc[j];
}

// =======================================================================
extern "C" void kernel_launch(void* const* d_in, const int* in_sizes, int n_in,
                              void* d_out, int out_size)
{
    (void)in_sizes; (void)n_in; (void)out_size;
    const int*   x          = (const int*)  d_in[0];
    const float* context    = (const float*)d_in[1];
    const float* tok_emb    = (const float*)d_in[2];
    const float* pos_emb    = (const float*)d_in[3];
    const float* ln1_g      = (const float*)d_in[4];
    const float* ln1_b      = (const float*)d_in[5];
    const float* in_w       = (const float*)d_in[6];
    const float* conv_w     = (const float*)d_in[7];
    const float* conv_b     = (const float*)d_in[8];
    const float* xproj_w    = (const float*)d_in[9];
    const float* dt_w       = (const float*)d_in[10];
    const float* dt_b       = (const float*)d_in[11];
    const float* A_log      = (const float*)d_in[12];
    const float* D_skip     = (const float*)d_in[13];
    const float* mamba_out_w= (const float*)d_in[14];
    const float* ln2_g      = (const float*)d_in[15];
    const float* ln2_b      = (const float*)d_in[16];
    const float* attn_in_w  = (const float*)d_in[17];
    const float* attn_in_b  = (const float*)d_in[18];
    const float* attn_out_w = (const float*)d_in[19];
    const float* attn_out_b = (const float*)d_in[20];
    const float* lnf_g      = (const float*)d_in[21];
    const float* lnf_b      = (const float*)d_in[22];
    const float* logit_w    = (const float*)d_in[23];
    const float* logit_b    = (const float*)d_in[24];
    float* outp = (float*)d_out;

    float *h, *nrm, *xz, *u, *xdbl, *delta, *y, *q, *kv, *ao;
    cudaGetSymbolAddress((void**)&h,    g_h);
    cudaGetSymbolAddress((void**)&nrm,  g_nrm);
    cudaGetSymbolAddress((void**)&xz,   g_xz);
    cudaGetSymbolAddress((void**)&u,    g_u);
    cudaGetSymbolAddress((void**)&xdbl, g_xdbl);
    cudaGetSymbolAddress((void**)&delta,g_delta);
    cudaGetSymbolAddress((void**)&y,    g_y);
    cudaGetSymbolAddress((void**)&q,    g_q);
    cudaGetSymbolAddress((void**)&kv,   g_kv);
    cudaGetSymbolAddress((void**)&ao,   g_ao);

    auto gemm = [](const float* A, int lda, const float* W, int ldw,
                   const float* bias, float* C, int ldc,
                   int M, int N, int K, int beta) {
        dim3 grid((N + BN - 1)/BN, (M + BM - 1)/BM);
        hgemm_k<<<grid, 256>>>(A, lda, W, ldw, bias, C, ldc, M, N, K, beta);
    };

    const int NTH = 256;
    const long KVSZ = (long)BB*CTXN*2*DIMV;

    // Launch order: embed(1), kv0(2), kv1(3), kv2(4), LN1(5), in_proj(6) <- ncu -s5 -c1
    embed_k<<<(NROWS*DIMV + NTH-1)/NTH, NTH>>>(x, tok_emb, pos_emb);

    // K/V depend only on context — hoist all layers, fused K|V (N=1024)
    for (int i = 0; i < DEPTHN; i++) {
        const float* aw = attn_in_w + (long)i*3*DIMV*DIMV;
        const float* ab = attn_in_b + (long)i*3*DIMV;
        gemm(context, DIMV, aw + (long)DIMV*DIMV, DIMV, ab + DIMV,
             kv + (long)i*KVSZ, 2*DIMV, BB*CTXN, 2*DIMV, DIMV, 0);
    }

    for (int i = 0; i < DEPTHN; i++) {
        // ---- mamba block ----
        layernorm_k<<<NROWS, 256>>>(h, ln1_g + i*DIMV, ln1_b + i*DIMV, nrm);
        gemm(nrm, DIMV, in_w + (long)i*2*DINNER*DIMV, DIMV, nullptr,
             xz, 2*DINNER, NROWS, 2*DINNER, DIMV, 0);
        conv_silu_k<<<(NROWS*DINNER + NTH-1)/NTH, NTH>>>(
            conv_w + (long)i*DINNER*DCONVN, conv_b + (long)i*DINNER);
        gemm(u, DINNER, xproj_w + (long)i*(DTRANK+2*DSTATE)*DINNER, DINNER, nullptr,
             xdbl, DTRANK+2*DSTATE, NROWS, DTRANK+2*DSTATE, DINNER, 0);
        gemm(xdbl, DTRANK+2*DSTATE, dt_w + (long)i*DINNER*DTRANK, DTRANK,
             dt_b + (long)i*DINNER, delta, DINNER, NROWS, DINNER, DTRANK, 0);
        softplus_k<<<(NROWS*DINNER + NTH-1)/NTH, NTH>>>();
        scan_k<<<dim3(DINNER/16, BB), 256>>>(
            A_log + (long)i*DINNER*DSTATE, D_skip + (long)i*DINNER);
        gate_k<<<(NROWS*DINNER + NTH-1)/NTH, NTH>>>();
        gemm(y, DINNER, mamba_out_w + (long)i*DIMV*DINNER, DINNER, nullptr,
             h, DIMV, NROWS, DIMV, DINNER, 1);          // fused residual add

        // ---- cross attention ----
        layernorm_k<<<NROWS, 256>>>(h, ln2_g + i*DIMV, ln2_b + i*DIMV, nrm);
        const float* aw = attn_in_w + (long)i*3*DIMV*DIMV;
        const float* ab = attn_in_b + (long)i*3*DIMV;
        gemm(nrm, DIMV, aw, DIMV, ab, q, DIMV, NROWS, DIMV, DIMV, 0);
        const float* kvi = kv + (long)i*KVSZ;
        attn_scores_k<<<dim3(BB*HEADSN, LL/128), 128>>>(kvi);
        softmax_k<<<(BB*HEADSN*LL)/8, 256>>>();
        attn_mean_k<<<(BB*LL*CTXN + NTH-1)/NTH, NTH>>>(
            outp + (long)BB*LL*VOCABN + (long)i*BB*LL*CTXN);
        attn_av_k<<<dim3(BB*HEADSN, LL/128), 128>>>(kvi);
        gemm(ao, DIMV, attn_out_w + (long)i*DIMV*DIMV, DIMV,
             attn_out_b + (long)i*DIMV, h, DIMV, NROWS, DIMV, DIMV, 1);  // fused add
    }

    // ---- final LN + logits ----
    layernorm_k<<<NROWS, 256>>>(h, lnf_g, lnf_b, nrm);
    gemm(nrm, DIMV, logit_w, DIMV, logit_b, outp, VOCABN, NROWS, VOCABN, DIMV, 0);
}